// round 10
// baseline (speedup 1.0000x reference)
#include <cuda_runtime.h>
#include <math.h>
#include <float.h>

#define NB    32
#define MROWS 100000
#define WC    64
#define RR    9
#define NIF   138
#define DIN   512
#define NBLK  37           // 37*32 = 1184 blocks
#define CHUNK 2703         // ceil(100000/37)
#define NCAND (NBLK*8)     // 296 candidates per batch
#define NPOOL (256 + RR)   // 32 producers x 8 + 9 patch rows
#define NPART 4            // d-partition blocks per batch in iface GEMM

// -------- scratch (no allocation allowed) --------
__device__ float g_part[NB][NPART][NIF];
__device__ float g_q[NB][WC];            // read_query
__device__ float g_rows[NB][RR][WC];     // updated memory rows at rp
__device__ float g_cand_d[NB][NCAND];
__device__ int   g_cand_i[NB][NCAND];
__device__ int   g_tick_if[NB];          // zero-initialized; self-resetting tickets
__device__ int   g_tick_sc[NB];

__device__ __forceinline__ bool lt_pair(float d1, int i1, float d2, int i2) {
    return d1 < d2 || (d1 == d2 && i1 < i2);
}

__device__ __forceinline__ float dist8(float4 v0, float4 v1, float4 qa, float4 qb) {
    float dx, acc;
    dx = v0.x - qa.x; acc  = dx * dx;
    dx = v0.y - qa.y; acc += dx * dx;
    dx = v0.z - qa.z; acc += dx * dx;
    dx = v0.w - qa.w; acc += dx * dx;
    dx = v1.x - qb.x; acc += dx * dx;
    dx = v1.y - qb.y; acc += dx * dx;
    dx = v1.z - qb.z; acc += dx * dx;
    dx = v1.w - qb.w; acc += dx * dx;
    return acc;
}

// insert with stale-row exclusion; all-register, predicated.
__device__ __forceinline__ void insert8x(float cv, int ci, float (&ld)[8], int (&lix)[8],
                                         const int* __restrict__ srp) {
    if (lt_pair(cv, ci, ld[7], lix[7])) {
        bool stale = false;
        #pragma unroll
        for (int k = 0; k < RR; k++) stale |= (srp[k] == ci);
        if (!stale) {
            #pragma unroll
            for (int k = 0; k < 8; k++) {
                bool sw = lt_pair(cv, ci, ld[k], lix[k]);
                float td = ld[k]; int ti = lix[k];
                if (sw) { ld[k] = cv; lix[k] = ci; cv = td; ci = ti; }
            }
        }
    }
}

// ================= Kernel 1: iface GEMM (fused partial + finish) =================
__global__ void k_iface(const float* __restrict__ xi, const float* __restrict__ Wm,
                        const float* __restrict__ b_lin, const float* __restrict__ usage,
                        const float* __restrict__ read_w, const float* __restrict__ rvec,
                        const int* __restrict__ rpos) {
    int b = blockIdx.y;
    int dbase = blockIdx.x * (DIN / NPART);
    __shared__ float sx[DIN / NPART];
    __shared__ float pp[4][NIF];
    __shared__ int slast;

    int tid = threadIdx.x;
    if (tid < DIN / NPART) sx[tid] = xi[b * DIN + dbase + tid];
    __syncthreads();

    int s = tid / NIF;
    int j = tid - s * NIF;
    if (s < 4) {
        int d0 = dbase + s * 32;
        float acc = 0.f;
        #pragma unroll
        for (int d = 0; d < 32; d++)
            acc = fmaf(sx[s * 32 + d], Wm[(d0 + d) * NIF + j], acc);
        pp[s][j] = acc;
    }
    __syncthreads();

    if (tid < NIF)
        g_part[b][blockIdx.x][tid] = pp[0][tid] + pp[1][tid] + pp[2][tid] + pp[3][tid];

    __threadfence();
    if (tid == 0) slast = (atomicAdd(&g_tick_if[b], 1) == NPART - 1);
    __syncthreads();
    if (!slast) return;
    if (tid == 0) g_tick_if[b] = 0;   // reset for next replay

    // ---- finish phase (only last block of batch b) ----
    __shared__ float sif[NIF];
    __shared__ float sww[RR];
    __shared__ float swv[WC];

    if (tid < NIF) {
        float acc = b_lin[tid];
        #pragma unroll
        for (int p = 0; p < NPART; p++) acc += __ldcg(&g_part[b][p][tid]);
        sif[tid] = acc;
        if (tid < WC) g_q[b][tid] = acc;                    // read_query
        if (tid >= WC && tid < 2 * WC) swv[tid - WC] = acc; // write_vector
    }
    __syncthreads();

    if (tid == 0) {
        float wg = 1.f / (1.f + expf(-sif[NIF - 1]));
        float rel[RR];
        float minu = INFINITY;
        #pragma unroll
        for (int k = 0; k < RR; k++) {
            int rp = rpos[b * RR + k];
            rel[k] = usage[(size_t)b * MROWS + rp];
            minu = fminf(minu, rel[k]);
        }
        #pragma unroll
        for (int k = 0; k < RR; k++) {
            float ig = 1.f / (1.f + expf(-sif[2 * WC + k]));
            float I  = (rel[k] == minu) ? 1.f : 0.f;
            sww[k] = wg * (ig * read_w[b * RR + k] + (1.f - ig) * I);
        }
    }
    __syncthreads();

    for (int t = tid; t < RR * WC; t += blockDim.x) {
        int k = t >> 6, w = t & 63;
        g_rows[b][k][w] = rvec[(b * RR + k) * WC + w] + sww[k] * swv[w];
    }
}

// ================= Kernel 2: streaming scan + fused final merge/gather =================
// UNROLL-BY-4: 8 independent float4 loads in flight per thread (128B/thread)
// to fill the loaded-latency (queuing) regime with more outstanding bytes.
__global__ void __launch_bounds__(256, 3) k_scan(const float* __restrict__ mem,
                                                 const int* __restrict__ rpos,
                                                 float* __restrict__ out) {
    const int b = blockIdx.y;
    const int row0 = blockIdx.x * CHUNK;
    const int row_end = min(row0 + CHUNK, MROWS);
    const int lane = threadIdx.x & 31;
    const int warp = threadIdx.x >> 5;
    const int li = lane & 7;     // 8 lanes per row
    const int pg = lane >> 3;    // 4 rows per warp per slot
    const unsigned gmask = 0xFFu << (pg * 8);

    __shared__ int srp[RR];
    __shared__ float sd[NCAND];   // pool (265) then final merge (296)
    __shared__ int   si[NCAND];
    __shared__ int slast;
    __shared__ int sel[8];
    if (threadIdx.x < RR) srp[threadIdx.x] = rpos[b * RR + threadIdx.x];
    __syncthreads();

    // q slices (contiguous layout: lane li covers floats [li*4,li*4+4) and [32+li*4,...))
    float4 qa = *(const float4*)&g_q[b][li * 4];
    float4 qb = *(const float4*)&g_q[b][32 + li * 4];

    float ld[8]; int lix[8];
    #pragma unroll
    for (int k = 0; k < 8; k++) { ld[k] = INFINITY; lix[k] = 0x7fffffff; }

    const float* base = mem + (size_t)b * MROWS * WC;
    int r = row0 + warp * 4 + pg;
    const float* pA = base + (size_t)r * WC + li * 4;

    // quad-unrolled: 8 float4 loads issued back-to-back; 128 rows per iteration
    int nfull4 = (row_end - row0) >> 7;
    for (int it = 0; it < nfull4; ++it) {
        float4 a0 = __ldcg((const float4*)pA);
        float4 a1 = __ldcg((const float4*)(pA + 32));
        float4 b0 = __ldcg((const float4*)(pA + 32 * WC));
        float4 b1 = __ldcg((const float4*)(pA + 32 * WC + 32));
        float4 c0 = __ldcg((const float4*)(pA + 64 * WC));
        float4 c1 = __ldcg((const float4*)(pA + 64 * WC + 32));
        float4 d0 = __ldcg((const float4*)(pA + 96 * WC));
        float4 d1 = __ldcg((const float4*)(pA + 96 * WC + 32));
        float accA = dist8(a0, a1, qa, qb);
        float accB = dist8(b0, b1, qa, qb);
        float accC = dist8(c0, c1, qa, qb);
        float accD = dist8(d0, d1, qa, qb);
        accA += __shfl_xor_sync(0xffffffffu, accA, 1);
        accA += __shfl_xor_sync(0xffffffffu, accA, 2);
        accA += __shfl_xor_sync(0xffffffffu, accA, 4);
        accB += __shfl_xor_sync(0xffffffffu, accB, 1);
        accB += __shfl_xor_sync(0xffffffffu, accB, 2);
        accB += __shfl_xor_sync(0xffffffffu, accB, 4);
        accC += __shfl_xor_sync(0xffffffffu, accC, 1);
        accC += __shfl_xor_sync(0xffffffffu, accC, 2);
        accC += __shfl_xor_sync(0xffffffffu, accC, 4);
        accD += __shfl_xor_sync(0xffffffffu, accD, 1);
        accD += __shfl_xor_sync(0xffffffffu, accD, 2);
        accD += __shfl_xor_sync(0xffffffffu, accD, 4);
        if (li == 0) {
            insert8x(accA, r,      ld, lix, srp);
            insert8x(accB, r + 32, ld, lix, srp);
            insert8x(accC, r + 64, ld, lix, srp);
            insert8x(accD, r + 96, ld, lix, srp);
        }
        r += 128; pA += 128 * WC;
    }
    // remainder: up to 127 rows -> 4 guarded single steps (32 rows each)
    #pragma unroll
    for (int t = 0; t < 4; ++t) {
        if (r < row_end) {
            float4 a0 = __ldcg((const float4*)pA);
            float4 a1 = __ldcg((const float4*)(pA + 32));
            float acc = dist8(a0, a1, qa, qb);
            acc += __shfl_xor_sync(gmask, acc, 1);
            acc += __shfl_xor_sync(gmask, acc, 2);
            acc += __shfl_xor_sync(gmask, acc, 4);
            if (li == 0) insert8x(acc, r, ld, lix, srp);
        }
        r += 32; pA += 32 * WC;
    }

    // producers dump sorted-8 to pool slots [0,256)
    if (li == 0) {
        int slot = threadIdx.x >> 3;
        #pragma unroll
        for (int k = 0; k < 8; k++) { sd[slot * 8 + k] = ld[k]; si[slot * 8 + k] = lix[k]; }
    }

    // warp 0: patch candidates for rp rows in this block's range (slots [256,265))
    if (warp == 0) {
        #pragma unroll
        for (int k = 0; k < RR; k++) {
            int rr = srp[k];
            bool use = (rr >= row0 && rr < row_end);
            #pragma unroll
            for (int k2 = k + 1; k2 < RR; k2++) use &= (srp[k2] != rr);  // last write wins
            float accv = 0.f;
            if (lane < 8) {
                float4 g0 = *(const float4*)&g_rows[b][k][lane * 4];
                float4 g1 = *(const float4*)&g_rows[b][k][32 + lane * 4];
                accv = dist8(g0, g1, qa, qb);
                accv += __shfl_xor_sync(0xFFu, accv, 1);
                accv += __shfl_xor_sync(0xFFu, accv, 2);
                accv += __shfl_xor_sync(0xFFu, accv, 4);
            }
            if (lane == 0) {
                sd[256 + k] = use ? accv : INFINITY;
                si[256 + k] = use ? rr   : 0x7fffffff;
            }
        }
    }
    __syncthreads();

    // merge pool (265 entries) -> block top-8 -> global candidate list
    if (threadIdx.x < 32) {
        int l = threadIdx.x;
        for (int s = 0; s < 8; s++) {
            float bd = INFINITY; int bi = 0x7fffffff; int bs = -1;
            for (int k = l; k < NPOOL; k += 32)
                if (lt_pair(sd[k], si[k], bd, bi)) { bd = sd[k]; bi = si[k]; bs = k; }
            #pragma unroll
            for (int off = 16; off; off >>= 1) {
                float od = __shfl_xor_sync(0xffffffffu, bd, off);
                int   oi = __shfl_xor_sync(0xffffffffu, bi, off);
                int   os = __shfl_xor_sync(0xffffffffu, bs, off);
                if (lt_pair(od, oi, bd, bi)) { bd = od; bi = oi; bs = os; }
            }
            if (l == 0) {
                g_cand_d[b][blockIdx.x * 8 + s] = bd;
                g_cand_i[b][blockIdx.x * 8 + s] = bi;
                if (bs >= 0) sd[bs] = INFINITY;
            }
            __syncwarp();
        }
    }

    // ---- ticket: last block of batch b performs the final merge + gather ----
    __threadfence();
    if (threadIdx.x == 0) slast = (atomicAdd(&g_tick_sc[b], 1) == NBLK - 1);
    __syncthreads();
    if (!slast) return;
    if (threadIdx.x == 0) g_tick_sc[b] = 0;   // reset for next replay

    for (int t = threadIdx.x; t < NCAND; t += blockDim.x) {
        sd[t] = __ldcg(&g_cand_d[b][t]);
        si[t] = __ldcg(&g_cand_i[b][t]);
    }
    __syncthreads();

    if (threadIdx.x < 32) {
        int l = threadIdx.x;
        for (int s = 0; s < 8; s++) {
            float bd = INFINITY; int bi = 0x7fffffff; int bs = -1;
            for (int k = l; k < NCAND; k += 32)
                if (lt_pair(sd[k], si[k], bd, bi)) { bd = sd[k]; bi = si[k]; bs = k; }
            #pragma unroll
            for (int off = 16; off; off >>= 1) {
                float od = __shfl_xor_sync(0xffffffffu, bd, off);
                int   oi = __shfl_xor_sync(0xffffffffu, bi, off);
                int   os = __shfl_xor_sync(0xffffffffu, bs, off);
                if (lt_pair(od, oi, bd, bi)) { bd = od; bi = oi; bs = os; }
            }
            if (l == 0) { sel[s] = bi; if (bs >= 0) sd[bs] = INFINITY; }
            __syncwarp();
        }
    }
    __syncthreads();

    for (int t = threadIdx.x; t < 8 * WC; t += blockDim.x) {
        int k = t >> 6, w = t & 63;
        int idx = sel[k];
        int src = -1;
        #pragma unroll
        for (int j = RR - 1; j >= 0; --j)
            if (src < 0 && srp[j] == idx) src = j;  // last write wins
        float v = (src >= 0) ? g_rows[b][src][w]
                             : __ldcg(&mem[((size_t)b * MROWS + idx) * WC + w]);
        out[(b * 8 + k) * WC + w] = v;
    }
}

// ================= launcher =================
extern "C" void kernel_launch(void* const* d_in, const int* in_sizes, int n_in,
                              void* d_out, int out_size) {
    const float* xi     = (const float*)d_in[0];
    const float* Wm     = (const float*)d_in[1];
    const float* b_lin  = (const float*)d_in[2];
    const float* mem    = (const float*)d_in[3];
    const float* usage  = (const float*)d_in[4];
    const float* read_w = (const float*)d_in[5];
    // d_in[6] write_weights: dead w.r.t. output
    const float* rvec   = (const float*)d_in[7];
    // d_in[8] last_used_mem: dead (only feeds rv[:,8,:] which is sliced off)
    const int*   rpos   = (const int*)d_in[9];
    // d_in[10] timestep: dead (only feeds usage update -> rw, never returned)
    float* out = (float*)d_out;

    k_iface<<<dim3(NPART, NB), 552>>>(xi, Wm, b_lin, usage, read_w, rvec, rpos);
    k_scan<<<dim3(NBLK, NB), 256>>>(mem, rpos, out);
}

// round 11
// speedup vs baseline: 1.1862x; 1.1862x over previous
#include <cuda_runtime.h>
#include <math.h>
#include <float.h>

#define NB    32
#define MROWS 100000
#define WC    64
#define RR    9
#define NIF   138
#define DIN   512
#define NBLK  37           // 37*32 = 1184 blocks
#define CHUNK 2703         // ceil(100000/37)
#define NCAND (NBLK*8)     // 296 candidates per batch
#define NPOOL (256 + RR)   // 32 producers x 8 + 9 patch rows
#define NPART 4            // d-partition blocks per batch in iface GEMM

// -------- scratch (no allocation allowed) --------
__device__ float g_part[NB][NPART][NIF];
__device__ float g_q[NB][WC];            // read_query
__device__ float g_rows[NB][RR][WC];     // updated memory rows at rp
__device__ float g_cand_d[NB][NCAND];
__device__ int   g_cand_i[NB][NCAND];
__device__ int   g_tick_if[NB];          // zero-initialized; self-resetting tickets
__device__ int   g_tick_sc[NB];

__device__ __forceinline__ bool lt_pair(float d1, int i1, float d2, int i2) {
    return d1 < d2 || (d1 == d2 && i1 < i2);
}

__device__ __forceinline__ float dist8(float4 v0, float4 v1, float4 qa, float4 qb) {
    float dx, acc;
    dx = v0.x - qa.x; acc  = dx * dx;
    dx = v0.y - qa.y; acc += dx * dx;
    dx = v0.z - qa.z; acc += dx * dx;
    dx = v0.w - qa.w; acc += dx * dx;
    dx = v1.x - qb.x; acc += dx * dx;
    dx = v1.y - qb.y; acc += dx * dx;
    dx = v1.z - qb.z; acc += dx * dx;
    dx = v1.w - qb.w; acc += dx * dx;
    return acc;
}

// ================= Kernel 1: iface GEMM (fused partial + finish) =================
__global__ void k_iface(const float* __restrict__ xi, const float* __restrict__ Wm,
                        const float* __restrict__ b_lin, const float* __restrict__ usage,
                        const float* __restrict__ read_w, const float* __restrict__ rvec,
                        const int* __restrict__ rpos) {
    int b = blockIdx.y;
    int dbase = blockIdx.x * (DIN / NPART);
    __shared__ float sx[DIN / NPART];
    __shared__ float pp[4][NIF];
    __shared__ int slast;

    int tid = threadIdx.x;
    if (tid < DIN / NPART) sx[tid] = xi[b * DIN + dbase + tid];
    __syncthreads();

    int s = tid / NIF;
    int j = tid - s * NIF;
    if (s < 4) {
        int d0 = dbase + s * 32;
        float acc = 0.f;
        #pragma unroll
        for (int d = 0; d < 32; d++)
            acc = fmaf(sx[s * 32 + d], Wm[(d0 + d) * NIF + j], acc);
        pp[s][j] = acc;
    }
    __syncthreads();

    if (tid < NIF)
        g_part[b][blockIdx.x][tid] = pp[0][tid] + pp[1][tid] + pp[2][tid] + pp[3][tid];

    __threadfence();
    if (tid == 0) slast = (atomicAdd(&g_tick_if[b], 1) == NPART - 1);
    __syncthreads();
    if (!slast) return;
    if (tid == 0) g_tick_if[b] = 0;   // reset for next replay

    // ---- finish phase (only last block of batch b) ----
    __shared__ float sif[NIF];
    __shared__ float sww[RR];
    __shared__ float swv[WC];

    if (tid < NIF) {
        float acc = b_lin[tid];
        #pragma unroll
        for (int p = 0; p < NPART; p++) acc += __ldcg(&g_part[b][p][tid]);
        sif[tid] = acc;
        if (tid < WC) g_q[b][tid] = acc;                    // read_query
        if (tid >= WC && tid < 2 * WC) swv[tid - WC] = acc; // write_vector
    }
    __syncthreads();

    if (tid == 0) {
        float wg = 1.f / (1.f + expf(-sif[NIF - 1]));
        float rel[RR];
        float minu = INFINITY;
        #pragma unroll
        for (int k = 0; k < RR; k++) {
            int rp = rpos[b * RR + k];
            rel[k] = usage[(size_t)b * MROWS + rp];
            minu = fminf(minu, rel[k]);
        }
        #pragma unroll
        for (int k = 0; k < RR; k++) {
            float ig = 1.f / (1.f + expf(-sif[2 * WC + k]));
            float I  = (rel[k] == minu) ? 1.f : 0.f;
            sww[k] = wg * (ig * read_w[b * RR + k] + (1.f - ig) * I);
        }
    }
    __syncthreads();

    for (int t = tid; t < RR * WC; t += blockDim.x) {
        int k = t >> 6, w = t & 63;
        g_rows[b][k][w] = rvec[(b * RR + k) * WC + w] + sww[k] * swv[w];
    }
}

// ================= Kernel 2: streaming scan + fused final merge/gather =================
// 48 warps/SM: regs capped at 40 via launch_bounds(256,6). The per-row guard
// touches only worst_d/worst_i registers; ld/lix arrays may spill to local --
// they are accessed only on the rare insert path.
__global__ void __launch_bounds__(256, 6) k_scan(const float* __restrict__ mem,
                                                 const int* __restrict__ rpos,
                                                 float* __restrict__ out) {
    const int b = blockIdx.y;
    const int row0 = blockIdx.x * CHUNK;
    const int row_end = min(row0 + CHUNK, MROWS);
    const int lane = threadIdx.x & 31;
    const int warp = threadIdx.x >> 5;
    const int li = lane & 7;     // 8 lanes per row
    const int pg = lane >> 3;    // 4 rows per warp
    const unsigned gmask = 0xFFu << (pg * 8);

    __shared__ int srp[RR];
    __shared__ float sd[NCAND];   // pool (265) then final merge (296)
    __shared__ int   si[NCAND];
    __shared__ int slast;
    __shared__ int sel[8];
    if (threadIdx.x < RR) srp[threadIdx.x] = rpos[b * RR + threadIdx.x];
    __syncthreads();

    // q slices (contiguous: lane li covers floats [li*4,li*4+4) and [32+li*4,...))
    float4 qa = *(const float4*)&g_q[b][li * 4];
    float4 qb = *(const float4*)&g_q[b][32 + li * 4];

    float ld[8]; int lix[8];
    #pragma unroll
    for (int k = 0; k < 8; k++) { ld[k] = INFINITY; lix[k] = 0x7fffffff; }
    float worst_d = INFINITY; int worst_i = 0x7fffffff;

    const float* base = mem + (size_t)b * MROWS * WC;
    int r = row0 + warp * 4 + pg;
    const float* pA = base + (size_t)r * WC + li * 4;

    // rare path: sorted insert (array access happens only here)
    auto insert_arr = [&](float cv, int ci) {
        bool stale = false;
        #pragma unroll
        for (int k = 0; k < RR; k++) stale |= (srp[k] == ci);
        if (!stale) {
            #pragma unroll
            for (int k = 0; k < 8; k++) {
                bool sw = lt_pair(cv, ci, ld[k], lix[k]);
                float td = ld[k]; int ti = lix[k];
                if (sw) { ld[k] = cv; lix[k] = ci; cv = td; ci = ti; }
            }
            worst_d = ld[7]; worst_i = lix[7];
        }
    };

    // unroll-by-2 pipeline: 4 float4 loads in flight per thread; 64 rows/iter
    int nfull2 = (row_end - row0) >> 6;
    for (int it = 0; it < nfull2; ++it) {
        float4 a0 = __ldcg((const float4*)pA);
        float4 a1 = __ldcg((const float4*)(pA + 32));
        float4 c0 = __ldcg((const float4*)(pA + 32 * WC));
        float4 c1 = __ldcg((const float4*)(pA + 32 * WC + 32));
        float accA = dist8(a0, a1, qa, qb);
        float accB = dist8(c0, c1, qa, qb);
        accA += __shfl_xor_sync(0xffffffffu, accA, 1);
        accA += __shfl_xor_sync(0xffffffffu, accA, 2);
        accA += __shfl_xor_sync(0xffffffffu, accA, 4);
        accB += __shfl_xor_sync(0xffffffffu, accB, 1);
        accB += __shfl_xor_sync(0xffffffffu, accB, 2);
        accB += __shfl_xor_sync(0xffffffffu, accB, 4);
        if (li == 0) {
            if (lt_pair(accA, r, worst_d, worst_i))      insert_arr(accA, r);
            if (lt_pair(accB, r + 32, worst_d, worst_i)) insert_arr(accB, r + 32);
        }
        r += 64; pA += 64 * WC;
    }
    // remainder: up to 63 rows -> 2 guarded single iterations
    #pragma unroll
    for (int t = 0; t < 2; ++t) {
        if (r < row_end) {
            float4 a0 = __ldcg((const float4*)pA);
            float4 a1 = __ldcg((const float4*)(pA + 32));
            float acc = dist8(a0, a1, qa, qb);
            acc += __shfl_xor_sync(gmask, acc, 1);
            acc += __shfl_xor_sync(gmask, acc, 2);
            acc += __shfl_xor_sync(gmask, acc, 4);
            if (li == 0 && lt_pair(acc, r, worst_d, worst_i)) insert_arr(acc, r);
        }
        r += 32; pA += 32 * WC;
    }

    // producers dump sorted-8 to pool slots [0,256)
    if (li == 0) {
        int slot = threadIdx.x >> 3;
        #pragma unroll
        for (int k = 0; k < 8; k++) { sd[slot * 8 + k] = ld[k]; si[slot * 8 + k] = lix[k]; }
    }

    // warp 0: patch candidates for rp rows in this block's range (slots [256,265))
    if (warp == 0) {
        #pragma unroll
        for (int k = 0; k < RR; k++) {
            int rr = srp[k];
            bool use = (rr >= row0 && rr < row_end);
            #pragma unroll
            for (int k2 = k + 1; k2 < RR; k2++) use &= (srp[k2] != rr);  // last write wins
            float accv = 0.f;
            if (lane < 8) {
                float4 g0 = *(const float4*)&g_rows[b][k][lane * 4];
                float4 g1 = *(const float4*)&g_rows[b][k][32 + lane * 4];
                accv = dist8(g0, g1, qa, qb);
                accv += __shfl_xor_sync(0xFFu, accv, 1);
                accv += __shfl_xor_sync(0xFFu, accv, 2);
                accv += __shfl_xor_sync(0xFFu, accv, 4);
            }
            if (lane == 0) {
                sd[256 + k] = use ? accv : INFINITY;
                si[256 + k] = use ? rr   : 0x7fffffff;
            }
        }
    }
    __syncthreads();

    // merge pool (265 entries) -> block top-8 -> global candidate list
    if (threadIdx.x < 32) {
        int l = threadIdx.x;
        for (int s = 0; s < 8; s++) {
            float bd = INFINITY; int bi = 0x7fffffff; int bs = -1;
            for (int k = l; k < NPOOL; k += 32)
                if (lt_pair(sd[k], si[k], bd, bi)) { bd = sd[k]; bi = si[k]; bs = k; }
            #pragma unroll
            for (int off = 16; off; off >>= 1) {
                float od = __shfl_xor_sync(0xffffffffu, bd, off);
                int   oi = __shfl_xor_sync(0xffffffffu, bi, off);
                int   os = __shfl_xor_sync(0xffffffffu, bs, off);
                if (lt_pair(od, oi, bd, bi)) { bd = od; bi = oi; bs = os; }
            }
            if (l == 0) {
                g_cand_d[b][blockIdx.x * 8 + s] = bd;
                g_cand_i[b][blockIdx.x * 8 + s] = bi;
                if (bs >= 0) sd[bs] = INFINITY;
            }
            __syncwarp();
        }
    }

    // ---- ticket: last block of batch b performs the final merge + gather ----
    __threadfence();
    if (threadIdx.x == 0) slast = (atomicAdd(&g_tick_sc[b], 1) == NBLK - 1);
    __syncthreads();
    if (!slast) return;
    if (threadIdx.x == 0) g_tick_sc[b] = 0;   // reset for next replay

    for (int t = threadIdx.x; t < NCAND; t += blockDim.x) {
        sd[t] = __ldcg(&g_cand_d[b][t]);
        si[t] = __ldcg(&g_cand_i[b][t]);
    }
    __syncthreads();

    if (threadIdx.x < 32) {
        int l = threadIdx.x;
        for (int s = 0; s < 8; s++) {
            float bd = INFINITY; int bi = 0x7fffffff; int bs = -1;
            for (int k = l; k < NCAND; k += 32)
                if (lt_pair(sd[k], si[k], bd, bi)) { bd = sd[k]; bi = si[k]; bs = k; }
            #pragma unroll
            for (int off = 16; off; off >>= 1) {
                float od = __shfl_xor_sync(0xffffffffu, bd, off);
                int   oi = __shfl_xor_sync(0xffffffffu, bi, off);
                int   os = __shfl_xor_sync(0xffffffffu, bs, off);
                if (lt_pair(od, oi, bd, bi)) { bd = od; bi = oi; bs = os; }
            }
            if (l == 0) { sel[s] = bi; if (bs >= 0) sd[bs] = INFINITY; }
            __syncwarp();
        }
    }
    __syncthreads();

    for (int t = threadIdx.x; t < 8 * WC; t += blockDim.x) {
        int k = t >> 6, w = t & 63;
        int idx = sel[k];
        int src = -1;
        #pragma unroll
        for (int j = RR - 1; j >= 0; --j)
            if (src < 0 && srp[j] == idx) src = j;  // last write wins
        float v = (src >= 0) ? g_rows[b][src][w]
                             : __ldcg(&mem[((size_t)b * MROWS + idx) * WC + w]);
        out[(b * 8 + k) * WC + w] = v;
    }
}

// ================= launcher =================
extern "C" void kernel_launch(void* const* d_in, const int* in_sizes, int n_in,
                              void* d_out, int out_size) {
    const float* xi     = (const float*)d_in[0];
    const float* Wm     = (const float*)d_in[1];
    const float* b_lin  = (const float*)d_in[2];
    const float* mem    = (const float*)d_in[3];
    const float* usage  = (const float*)d_in[4];
    const float* read_w = (const float*)d_in[5];
    // d_in[6] write_weights: dead w.r.t. output
    const float* rvec   = (const float*)d_in[7];
    // d_in[8] last_used_mem: dead (only feeds rv[:,8,:] which is sliced off)
    const int*   rpos   = (const int*)d_in[9];
    // d_in[10] timestep: dead (only feeds usage update -> rw, never returned)
    float* out = (float*)d_out;

    k_iface<<<dim3(NPART, NB), 552>>>(xi, Wm, b_lin, usage, read_w, rvec, rpos);
    k_scan<<<dim3(NBLK, NB), 256>>>(mem, rpos, out);
}

// round 12
// speedup vs baseline: 1.4685x; 1.2380x over previous
#include <cuda_runtime.h>
#include <math.h>
#include <float.h>
#include <stdint.h>

#define NB    32
#define MROWS 100000
#define WC    64
#define RR    9
#define NIF   138
#define DIN   512
#define NBLK  9            // 9*32 = 288 blocks, 2/SM, single wave
#define CHUNK 11112        // ceil(100000/9)
#define NCAND (NBLK*8)     // 72 candidates per batch
#define NPROD 16           // producers per block (one per 4 rows... 16 row-slots)
#define NPOOL (NPROD*8 + RR)   // 137
#define NPART 4
#define NSTAGE 5
#define TROWS  64
#define TBYTES (TROWS * WC * 4)   // 16384
#define SMEM_DYN (NSTAGE * TBYTES)

// -------- scratch (no allocation allowed) --------
__device__ float g_part[NB][NPART][NIF];
__device__ float g_q[NB][WC];
__device__ float g_rows[NB][RR][WC];
__device__ float g_cand_d[NB][NCAND];
__device__ int   g_cand_i[NB][NCAND];
__device__ int   g_tick_if[NB];
__device__ int   g_tick_sc[NB];

__device__ __forceinline__ bool lt_pair(float d1, int i1, float d2, int i2) {
    return d1 < d2 || (d1 == d2 && i1 < i2);
}

__device__ __forceinline__ uint32_t smem_u32(const void* p) {
    uint32_t a;
    asm("{ .reg .u64 t; cvta.to.shared.u64 t, %1; cvt.u32.u64 %0, t; }" : "=r"(a) : "l"(p));
    return a;
}

__device__ __forceinline__ void mbar_init(uint32_t addr, uint32_t cnt) {
    asm volatile("mbarrier.init.shared.b64 [%0], %1;" :: "r"(addr), "r"(cnt) : "memory");
}
__device__ __forceinline__ void mbar_expect_tx(uint32_t addr, uint32_t bytes) {
    asm volatile("mbarrier.arrive.expect_tx.shared.b64 _, [%0], %1;" :: "r"(addr), "r"(bytes) : "memory");
}
__device__ __forceinline__ void mbar_wait(uint32_t addr, uint32_t parity) {
    asm volatile(
        "{\n\t.reg .pred P;\n\t"
        "WAIT_%=:\n\t"
        "mbarrier.try_wait.parity.acquire.cta.shared::cta.b64 P, [%0], %1, 0x989680;\n\t"
        "@P bra.uni DONE_%=;\n\t"
        "bra.uni WAIT_%=;\n\t"
        "DONE_%=:\n\t}"
        :: "r"(addr), "r"(parity) : "memory");
}
__device__ __forceinline__ void bulk_g2s(uint32_t dst, const void* src, uint32_t bytes, uint32_t mbar) {
    asm volatile("cp.async.bulk.shared::cta.global.mbarrier::complete_tx::bytes [%0], [%1], %2, [%3];"
                 :: "r"(dst), "l"(src), "r"(bytes), "r"(mbar) : "memory");
}

// ================= Kernel 1: iface GEMM (fused partial + finish) =================
__global__ void k_iface(const float* __restrict__ xi, const float* __restrict__ Wm,
                        const float* __restrict__ b_lin, const float* __restrict__ usage,
                        const float* __restrict__ read_w, const float* __restrict__ rvec,
                        const int* __restrict__ rpos) {
    int b = blockIdx.y;
    int dbase = blockIdx.x * (DIN / NPART);
    __shared__ float sx[DIN / NPART];
    __shared__ float pp[4][NIF];
    __shared__ int slast;

    int tid = threadIdx.x;
    if (tid < DIN / NPART) sx[tid] = xi[b * DIN + dbase + tid];
    __syncthreads();

    int s = tid / NIF;
    int j = tid - s * NIF;
    if (s < 4) {
        int d0 = dbase + s * 32;
        float acc = 0.f;
        #pragma unroll
        for (int d = 0; d < 32; d++)
            acc = fmaf(sx[s * 32 + d], Wm[(d0 + d) * NIF + j], acc);
        pp[s][j] = acc;
    }
    __syncthreads();

    if (tid < NIF)
        g_part[b][blockIdx.x][tid] = pp[0][tid] + pp[1][tid] + pp[2][tid] + pp[3][tid];

    __threadfence();
    if (tid == 0) slast = (atomicAdd(&g_tick_if[b], 1) == NPART - 1);
    __syncthreads();
    if (!slast) return;
    if (tid == 0) g_tick_if[b] = 0;

    __shared__ float sif[NIF];
    __shared__ float sww[RR];
    __shared__ float swv[WC];

    if (tid < NIF) {
        float acc = b_lin[tid];
        #pragma unroll
        for (int p = 0; p < NPART; p++) acc += __ldcg(&g_part[b][p][tid]);
        sif[tid] = acc;
        if (tid < WC) g_q[b][tid] = acc;
        if (tid >= WC && tid < 2 * WC) swv[tid - WC] = acc;
    }
    __syncthreads();

    if (tid == 0) {
        float wg = 1.f / (1.f + expf(-sif[NIF - 1]));
        float rel[RR];
        float minu = INFINITY;
        #pragma unroll
        for (int k = 0; k < RR; k++) {
            int rp = rpos[b * RR + k];
            rel[k] = usage[(size_t)b * MROWS + rp];
            minu = fminf(minu, rel[k]);
        }
        #pragma unroll
        for (int k = 0; k < RR; k++) {
            float ig = 1.f / (1.f + expf(-sif[2 * WC + k]));
            float I  = (rel[k] == minu) ? 1.f : 0.f;
            sww[k] = wg * (ig * read_w[b * RR + k] + (1.f - ig) * I);
        }
    }
    __syncthreads();

    for (int t = tid; t < RR * WC; t += blockDim.x) {
        int k = t >> 6, w = t & 63;
        g_rows[b][k][w] = rvec[(b * RR + k) * WC + w] + sww[k] * swv[w];
    }
}

// ================= Kernel 2: TMA-pipelined scan + fused final merge/gather =================
// 5-stage cp.async.bulk pipeline, 16KB tiles; consumers read smem coalesced.
__global__ void __launch_bounds__(256, 2) k_scan(const float* __restrict__ mem,
                                                 const int* __restrict__ rpos,
                                                 float* __restrict__ out) {
    extern __shared__ __align__(128) char dynsmem[];
    const int b = blockIdx.y;
    const int row0 = blockIdx.x * CHUNK;
    const int row_end = min(row0 + CHUNK, MROWS);
    const int tid = threadIdx.x;
    const int lane = tid & 31;
    const int warp = tid >> 5;

    __shared__ __align__(8) unsigned long long mbar[NSTAGE];
    __shared__ int srp[RR];
    __shared__ float sd[NPOOL];
    __shared__ int   si[NPOOL];
    __shared__ int slast;
    __shared__ int sel[8];

    if (tid < RR) srp[tid] = rpos[b * RR + tid];
    if (tid < NSTAGE) mbar_init(smem_u32(&mbar[tid]), 1);
    __syncthreads();

    const int nrows = row_end - row0;
    const int ntiles = (nrows + TROWS - 1) / TROWS;
    const float* base = mem + (size_t)b * MROWS * WC;
    const uint32_t smem_base = smem_u32(dynsmem);

    // prologue: issue first NSTAGE tiles
    if (tid == 0) {
        int npro = min(NSTAGE, ntiles);
        for (int t = 0; t < npro; ++t) {
            int tr = min(TROWS, nrows - t * TROWS);
            uint32_t bytes = (uint32_t)tr * WC * 4;
            uint32_t mb = smem_u32(&mbar[t]);
            mbar_expect_tx(mb, bytes);
            bulk_g2s(smem_base + t * TBYTES, base + (size_t)(row0 + t * TROWS) * WC, bytes, mb);
        }
    }

    // q piece: floats [(tid&15)*4, +4)
    float4 qp = *(const float4*)&g_q[b][(tid & 15) * 4];

    float ld[8]; int lix[8];
    #pragma unroll
    for (int k = 0; k < 8; k++) { ld[k] = INFINITY; lix[k] = 0x7fffffff; }
    const bool is_prod = ((lane & 15) == 0);
    const int rbase = tid >> 4;    // row slot 0..15 within tile

    for (int t = 0; t < ntiles; ++t) {
        int s = t % NSTAGE;
        uint32_t mb = smem_u32(&mbar[s]);
        mbar_wait(mb, (t / NSTAGE) & 1);

        const char* stg = dynsmem + s * TBYTES;
        float acc0, acc1, acc2, acc3;
        {
            const float4 v0 = *(const float4*)(stg + tid * 16);
            const float4 v1 = *(const float4*)(stg + tid * 16 + 4096);
            const float4 v2 = *(const float4*)(stg + tid * 16 + 8192);
            const float4 v3 = *(const float4*)(stg + tid * 16 + 12288);
            float dx;
            dx = v0.x - qp.x; acc0  = dx * dx;
            dx = v0.y - qp.y; acc0 += dx * dx;
            dx = v0.z - qp.z; acc0 += dx * dx;
            dx = v0.w - qp.w; acc0 += dx * dx;
            dx = v1.x - qp.x; acc1  = dx * dx;
            dx = v1.y - qp.y; acc1 += dx * dx;
            dx = v1.z - qp.z; acc1 += dx * dx;
            dx = v1.w - qp.w; acc1 += dx * dx;
            dx = v2.x - qp.x; acc2  = dx * dx;
            dx = v2.y - qp.y; acc2 += dx * dx;
            dx = v2.z - qp.z; acc2 += dx * dx;
            dx = v2.w - qp.w; acc2 += dx * dx;
            dx = v3.x - qp.x; acc3  = dx * dx;
            dx = v3.y - qp.y; acc3 += dx * dx;
            dx = v3.z - qp.z; acc3 += dx * dx;
            dx = v3.w - qp.w; acc3 += dx * dx;
        }
        #pragma unroll
        for (int off = 1; off <= 8; off <<= 1) {
            acc0 += __shfl_xor_sync(0xffffffffu, acc0, off);
            acc1 += __shfl_xor_sync(0xffffffffu, acc1, off);
            acc2 += __shfl_xor_sync(0xffffffffu, acc2, off);
            acc3 += __shfl_xor_sync(0xffffffffu, acc3, off);
        }
        if (is_prod) {
            int g0 = row0 + t * TROWS + rbase;
            float av[4] = {acc0, acc1, acc2, acc3};
            #pragma unroll
            for (int k = 0; k < 4; k++) {
                int gr = g0 + 16 * k;
                float cv = av[k];
                if (gr < row_end && lt_pair(cv, gr, ld[7], lix[7])) {
                    bool stale = false;
                    #pragma unroll
                    for (int j = 0; j < RR; j++) stale |= (srp[j] == gr);
                    if (!stale) {
                        int ci = gr;
                        #pragma unroll
                        for (int j = 0; j < 8; j++) {
                            bool sw = lt_pair(cv, ci, ld[j], lix[j]);
                            float td = ld[j]; int ti = lix[j];
                            if (sw) { ld[j] = cv; lix[j] = ci; cv = td; ci = ti; }
                        }
                    }
                }
            }
        }
        __syncthreads();   // all consumed stage s
        int tn = t + NSTAGE;
        if (tid == 0 && tn < ntiles) {
            int tr = min(TROWS, nrows - tn * TROWS);
            uint32_t bytes = (uint32_t)tr * WC * 4;
            mbar_expect_tx(mb, bytes);
            bulk_g2s(smem_base + s * TBYTES, base + (size_t)(row0 + tn * TROWS) * WC, bytes, mb);
        }
    }

    // producers dump sorted-8 to pool [0,128)
    if (is_prod) {
        #pragma unroll
        for (int k = 0; k < 8; k++) { sd[rbase * 8 + k] = ld[k]; si[rbase * 8 + k] = lix[k]; }
    }

    // warp 0: patch candidates for rp rows in range (slots [128,137))
    if (warp == 0) {
        #pragma unroll
        for (int k = 0; k < RR; k++) {
            int rr = srp[k];
            bool use = (rr >= row0 && rr < row_end);
            #pragma unroll
            for (int k2 = k + 1; k2 < RR; k2++) use &= (srp[k2] != rr);  // last write wins
            float accv = 0.f;
            if (lane < 16) {
                float4 g0 = *(const float4*)&g_rows[b][k][lane * 4];
                float dx;
                dx = g0.x - qp.x; accv  = dx * dx;   // qp of lane<16 matches piece lane
                dx = g0.y - qp.y; accv += dx * dx;
                dx = g0.z - qp.z; accv += dx * dx;
                dx = g0.w - qp.w; accv += dx * dx;
                #pragma unroll
                for (int off = 1; off <= 8; off <<= 1)
                    accv += __shfl_xor_sync(0xFFFFu, accv, off);
            }
            if (lane == 0) {
                sd[NPROD * 8 + k] = use ? accv : INFINITY;
                si[NPROD * 8 + k] = use ? rr   : 0x7fffffff;
            }
        }
    }
    __syncthreads();

    // merge pool (137) -> block top-8 -> global candidates
    if (tid < 32) {
        int l = tid;
        for (int s = 0; s < 8; s++) {
            float bd = INFINITY; int bi = 0x7fffffff; int bs = -1;
            for (int k = l; k < NPOOL; k += 32)
                if (lt_pair(sd[k], si[k], bd, bi)) { bd = sd[k]; bi = si[k]; bs = k; }
            #pragma unroll
            for (int off = 16; off; off >>= 1) {
                float od = __shfl_xor_sync(0xffffffffu, bd, off);
                int   oi = __shfl_xor_sync(0xffffffffu, bi, off);
                int   os = __shfl_xor_sync(0xffffffffu, bs, off);
                if (lt_pair(od, oi, bd, bi)) { bd = od; bi = oi; bs = os; }
            }
            if (l == 0) {
                g_cand_d[b][blockIdx.x * 8 + s] = bd;
                g_cand_i[b][blockIdx.x * 8 + s] = bi;
                if (bs >= 0) sd[bs] = INFINITY;
            }
            __syncwarp();
        }
    }

    // ticket: last block of batch b does final merge + gather
    __threadfence();
    if (tid == 0) slast = (atomicAdd(&g_tick_sc[b], 1) == NBLK - 1);
    __syncthreads();
    if (!slast) return;
    if (tid == 0) g_tick_sc[b] = 0;

    if (tid < NCAND) {
        sd[tid] = __ldcg(&g_cand_d[b][tid]);
        si[tid] = __ldcg(&g_cand_i[b][tid]);
    }
    __syncthreads();

    if (tid < 32) {
        int l = tid;
        for (int s = 0; s < 8; s++) {
            float bd = INFINITY; int bi = 0x7fffffff; int bs = -1;
            for (int k = l; k < NCAND; k += 32)
                if (lt_pair(sd[k], si[k], bd, bi)) { bd = sd[k]; bi = si[k]; bs = k; }
            #pragma unroll
            for (int off = 16; off; off >>= 1) {
                float od = __shfl_xor_sync(0xffffffffu, bd, off);
                int   oi = __shfl_xor_sync(0xffffffffu, bi, off);
                int   os = __shfl_xor_sync(0xffffffffu, bs, off);
                if (lt_pair(od, oi, bd, bi)) { bd = od; bi = oi; bs = os; }
            }
            if (l == 0) { sel[s] = bi; if (bs >= 0) sd[bs] = INFINITY; }
            __syncwarp();
        }
    }
    __syncthreads();

    for (int t = tid; t < 8 * WC; t += blockDim.x) {
        int k = t >> 6, w = t & 63;
        int idx = sel[k];
        int src = -1;
        #pragma unroll
        for (int j = RR - 1; j >= 0; --j)
            if (src < 0 && srp[j] == idx) src = j;
        float v = (src >= 0) ? g_rows[b][src][w]
                             : __ldcg(&mem[((size_t)b * MROWS + idx) * WC + w]);
        out[(b * 8 + k) * WC + w] = v;
    }
}

// ================= launcher =================
extern "C" void kernel_launch(void* const* d_in, const int* in_sizes, int n_in,
                              void* d_out, int out_size) {
    const float* xi     = (const float*)d_in[0];
    const float* Wm     = (const float*)d_in[1];
    const float* b_lin  = (const float*)d_in[2];
    const float* mem    = (const float*)d_in[3];
    const float* usage  = (const float*)d_in[4];
    const float* read_w = (const float*)d_in[5];
    const float* rvec   = (const float*)d_in[7];
    const int*   rpos   = (const int*)d_in[9];
    float* out = (float*)d_out;

    static int smem_set = 0;
    if (!smem_set) {
        cudaFuncSetAttribute(k_scan, cudaFuncAttributeMaxDynamicSharedMemorySize, SMEM_DYN);
        smem_set = 1;
    }

    k_iface<<<dim3(NPART, NB), 552>>>(xi, Wm, b_lin, usage, read_w, rvec, rpos);
    k_scan<<<dim3(NBLK, NB), 256, SMEM_DYN>>>(mem, rpos, out);
}

// round 13
// speedup vs baseline: 1.6665x; 1.1348x over previous
#include <cuda_runtime.h>
#include <math.h>
#include <float.h>
#include <stdint.h>

#define NB    32
#define MROWS 100000
#define WC    64
#define RR    9
#define NIF   138
#define DIN   512
#define NBLK  18           // 18*32 = 576 blocks, 4/SM
#define CHUNK 5556         // ceil(100000/18)
#define NCAND (NBLK*8)     // 144 candidates per batch
#define NPROD 16
#define NPOOL (NPROD*8 + RR)   // 137
#define NPART 4
#define NSTAGE 3
#define TROWS  64
#define TBYTES (TROWS * WC * 4)   // 16384
#define SMEM_DYN (NSTAGE * TBYTES)  // 48KB

// -------- scratch (no allocation allowed) --------
__device__ float g_part[NB][NPART][NIF];
__device__ float g_q[NB][WC];
__device__ float g_rows[NB][RR][WC];
__device__ float g_cand_d[NB][NCAND];
__device__ int   g_cand_i[NB][NCAND];
__device__ int   g_tick_if[NB];
__device__ int   g_tick_sc[NB];

__device__ __forceinline__ bool lt_pair(float d1, int i1, float d2, int i2) {
    return d1 < d2 || (d1 == d2 && i1 < i2);
}

__device__ __forceinline__ uint32_t smem_u32(const void* p) {
    uint32_t a;
    asm("{ .reg .u64 t; cvta.to.shared.u64 t, %1; cvt.u32.u64 %0, t; }" : "=r"(a) : "l"(p));
    return a;
}
__device__ __forceinline__ void mbar_init(uint32_t addr, uint32_t cnt) {
    asm volatile("mbarrier.init.shared.b64 [%0], %1;" :: "r"(addr), "r"(cnt) : "memory");
}
__device__ __forceinline__ void mbar_expect_tx(uint32_t addr, uint32_t bytes) {
    asm volatile("mbarrier.arrive.expect_tx.shared.b64 _, [%0], %1;" :: "r"(addr), "r"(bytes) : "memory");
}
__device__ __forceinline__ void mbar_wait(uint32_t addr, uint32_t parity) {
    asm volatile(
        "{\n\t.reg .pred P;\n\t"
        "WAIT_%=:\n\t"
        "mbarrier.try_wait.parity.acquire.cta.shared::cta.b64 P, [%0], %1, 0x989680;\n\t"
        "@P bra.uni DONE_%=;\n\t"
        "bra.uni WAIT_%=;\n\t"
        "DONE_%=:\n\t}"
        :: "r"(addr), "r"(parity) : "memory");
}
__device__ __forceinline__ void bulk_g2s(uint32_t dst, const void* src, uint32_t bytes, uint32_t mbar) {
    asm volatile("cp.async.bulk.shared::cta.global.mbarrier::complete_tx::bytes [%0], [%1], %2, [%3];"
                 :: "r"(dst), "l"(src), "r"(bytes), "r"(mbar) : "memory");
}

// ================= Kernel 1: iface GEMM (fused partial + finish) =================
__global__ void k_iface(const float* __restrict__ xi, const float* __restrict__ Wm,
                        const float* __restrict__ b_lin, const float* __restrict__ usage,
                        const float* __restrict__ read_w, const float* __restrict__ rvec,
                        const int* __restrict__ rpos) {
    int b = blockIdx.y;
    int dbase = blockIdx.x * (DIN / NPART);
    __shared__ float sx[DIN / NPART];
    __shared__ float pp[4][NIF];
    __shared__ int slast;

    int tid = threadIdx.x;
    if (tid < DIN / NPART) sx[tid] = xi[b * DIN + dbase + tid];
    __syncthreads();

    int s = tid / NIF;
    int j = tid - s * NIF;
    if (s < 4) {
        int d0 = dbase + s * 32;
        float acc = 0.f;
        #pragma unroll
        for (int d = 0; d < 32; d++)
            acc = fmaf(sx[s * 32 + d], Wm[(d0 + d) * NIF + j], acc);
        pp[s][j] = acc;
    }
    __syncthreads();

    if (tid < NIF)
        g_part[b][blockIdx.x][tid] = pp[0][tid] + pp[1][tid] + pp[2][tid] + pp[3][tid];

    __threadfence();
    if (tid == 0) slast = (atomicAdd(&g_tick_if[b], 1) == NPART - 1);
    __syncthreads();
    if (!slast) return;
    if (tid == 0) g_tick_if[b] = 0;

    __shared__ float sif[NIF];
    __shared__ float sww[RR];
    __shared__ float swv[WC];

    if (tid < NIF) {
        float acc = b_lin[tid];
        #pragma unroll
        for (int p = 0; p < NPART; p++) acc += __ldcg(&g_part[b][p][tid]);
        sif[tid] = acc;
        if (tid < WC) g_q[b][tid] = acc;
        if (tid >= WC && tid < 2 * WC) swv[tid - WC] = acc;
    }
    __syncthreads();

    if (tid == 0) {
        float wg = 1.f / (1.f + expf(-sif[NIF - 1]));
        float rel[RR];
        float minu = INFINITY;
        #pragma unroll
        for (int k = 0; k < RR; k++) {
            int rp = rpos[b * RR + k];
            rel[k] = usage[(size_t)b * MROWS + rp];
            minu = fminf(minu, rel[k]);
        }
        #pragma unroll
        for (int k = 0; k < RR; k++) {
            float ig = 1.f / (1.f + expf(-sif[2 * WC + k]));
            float I  = (rel[k] == minu) ? 1.f : 0.f;
            sww[k] = wg * (ig * read_w[b * RR + k] + (1.f - ig) * I);
        }
    }
    __syncthreads();

    for (int t = tid; t < RR * WC; t += blockDim.x) {
        int k = t >> 6, w = t & 63;
        g_rows[b][k][w] = rvec[(b * RR + k) * WC + w] + sww[k] * swv[w];
    }
}

// ================= Kernel 2: TMA-pipelined scan + fused final merge/gather =================
// 3-stage cp.async.bulk pipeline, 16KB tiles, 4 blocks/SM (32 consuming warps).
// Next-tile TMA issued right after mbar_wait (previous iteration's syncthreads
// guarantees the target slot is drained).
__global__ void __launch_bounds__(256, 4) k_scan(const float* __restrict__ mem,
                                                 const int* __restrict__ rpos,
                                                 float* __restrict__ out) {
    extern __shared__ __align__(128) char dynsmem[];
    const int b = blockIdx.y;
    const int row0 = blockIdx.x * CHUNK;
    const int row_end = min(row0 + CHUNK, MROWS);
    const int tid = threadIdx.x;
    const int lane = tid & 31;
    const int warp = tid >> 5;

    __shared__ __align__(8) unsigned long long mbar[NSTAGE];
    __shared__ int srp[RR];
    __shared__ float sd[NCAND];
    __shared__ int   si[NCAND];
    __shared__ int slast;
    __shared__ int sel[8];

    if (tid < RR) srp[tid] = rpos[b * RR + tid];
    if (tid < NSTAGE) mbar_init(smem_u32(&mbar[tid]), 1);
    __syncthreads();

    const int nrows = row_end - row0;
    const int ntiles = (nrows + TROWS - 1) / TROWS;
    const float* base = mem + (size_t)b * MROWS * WC;
    const uint32_t smem_base = smem_u32(dynsmem);

    // prologue: issue first NSTAGE tiles
    if (tid == 0) {
        int npro = min(NSTAGE, ntiles);
        for (int t = 0; t < npro; ++t) {
            int tr = min(TROWS, nrows - t * TROWS);
            uint32_t bytes = (uint32_t)tr * WC * 4;
            uint32_t mb = smem_u32(&mbar[t]);
            mbar_expect_tx(mb, bytes);
            bulk_g2s(smem_base + t * TBYTES, base + (size_t)(row0 + t * TROWS) * WC, bytes, mb);
        }
    }

    // q piece: floats [(tid&15)*4, +4)
    float4 qp = *(const float4*)&g_q[b][(tid & 15) * 4];

    float ld[8]; int lix[8];
    #pragma unroll
    for (int k = 0; k < 8; k++) { ld[k] = INFINITY; lix[k] = 0x7fffffff; }
    const bool is_prod = ((lane & 15) == 0);
    const int rbase = tid >> 4;    // row slot 0..15 within tile

    for (int t = 0; t < ntiles; ++t) {
        int s = t % NSTAGE;
        uint32_t mb = smem_u32(&mbar[s]);
        mbar_wait(mb, (t / NSTAGE) & 1);

        // issue tile (t-1)+NSTAGE into slot (t-1)%NSTAGE: that slot was fully
        // consumed before the syncthreads at the end of iteration t-1.
        if (t > 0 && tid == 0) {
            int tn = (t - 1) + NSTAGE;
            if (tn < ntiles) {
                int s2 = (t - 1) % NSTAGE;
                int tr = min(TROWS, nrows - tn * TROWS);
                uint32_t bytes = (uint32_t)tr * WC * 4;
                uint32_t mb2 = smem_u32(&mbar[s2]);
                mbar_expect_tx(mb2, bytes);
                bulk_g2s(smem_base + s2 * TBYTES, base + (size_t)(row0 + tn * TROWS) * WC, bytes, mb2);
            }
        }

        const char* stg = dynsmem + s * TBYTES;
        float acc0, acc1, acc2, acc3;
        {
            const float4 v0 = *(const float4*)(stg + tid * 16);
            const float4 v1 = *(const float4*)(stg + tid * 16 + 4096);
            const float4 v2 = *(const float4*)(stg + tid * 16 + 8192);
            const float4 v3 = *(const float4*)(stg + tid * 16 + 12288);
            float dx;
            dx = v0.x - qp.x; acc0  = dx * dx;
            dx = v0.y - qp.y; acc0 += dx * dx;
            dx = v0.z - qp.z; acc0 += dx * dx;
            dx = v0.w - qp.w; acc0 += dx * dx;
            dx = v1.x - qp.x; acc1  = dx * dx;
            dx = v1.y - qp.y; acc1 += dx * dx;
            dx = v1.z - qp.z; acc1 += dx * dx;
            dx = v1.w - qp.w; acc1 += dx * dx;
            dx = v2.x - qp.x; acc2  = dx * dx;
            dx = v2.y - qp.y; acc2 += dx * dx;
            dx = v2.z - qp.z; acc2 += dx * dx;
            dx = v2.w - qp.w; acc2 += dx * dx;
            dx = v3.x - qp.x; acc3  = dx * dx;
            dx = v3.y - qp.y; acc3 += dx * dx;
            dx = v3.z - qp.z; acc3 += dx * dx;
            dx = v3.w - qp.w; acc3 += dx * dx;
        }
        #pragma unroll
        for (int off = 1; off <= 8; off <<= 1) {
            acc0 += __shfl_xor_sync(0xffffffffu, acc0, off);
            acc1 += __shfl_xor_sync(0xffffffffu, acc1, off);
            acc2 += __shfl_xor_sync(0xffffffffu, acc2, off);
            acc3 += __shfl_xor_sync(0xffffffffu, acc3, off);
        }
        if (is_prod) {
            int g0 = row0 + t * TROWS + rbase;
            float av[4] = {acc0, acc1, acc2, acc3};
            #pragma unroll
            for (int k = 0; k < 4; k++) {
                int gr = g0 + 16 * k;
                float cv = av[k];
                if (gr < row_end && lt_pair(cv, gr, ld[7], lix[7])) {
                    bool stale = false;
                    #pragma unroll
                    for (int j = 0; j < RR; j++) stale |= (srp[j] == gr);
                    if (!stale) {
                        int ci = gr;
                        #pragma unroll
                        for (int j = 0; j < 8; j++) {
                            bool sw = lt_pair(cv, ci, ld[j], lix[j]);
                            float td = ld[j]; int ti = lix[j];
                            if (sw) { ld[j] = cv; lix[j] = ci; cv = td; ci = ti; }
                        }
                    }
                }
            }
        }
        __syncthreads();   // stage s fully consumed (enables issue at iter t+1)
    }

    // producers dump sorted-8 to pool [0,128)
    if (is_prod) {
        #pragma unroll
        for (int k = 0; k < 8; k++) { sd[rbase * 8 + k] = ld[k]; si[rbase * 8 + k] = lix[k]; }
    }

    // warp 0: patch candidates for rp rows in range (slots [128,137))
    if (warp == 0) {
        #pragma unroll
        for (int k = 0; k < RR; k++) {
            int rr = srp[k];
            bool use = (rr >= row0 && rr < row_end);
            #pragma unroll
            for (int k2 = k + 1; k2 < RR; k2++) use &= (srp[k2] != rr);  // last write wins
            float accv = 0.f;
            if (lane < 16) {
                float4 g0 = *(const float4*)&g_rows[b][k][lane * 4];
                float dx;
                dx = g0.x - qp.x; accv  = dx * dx;
                dx = g0.y - qp.y; accv += dx * dx;
                dx = g0.z - qp.z; accv += dx * dx;
                dx = g0.w - qp.w; accv += dx * dx;
                #pragma unroll
                for (int off = 1; off <= 8; off <<= 1)
                    accv += __shfl_xor_sync(0xFFFFu, accv, off);
            }
            if (lane == 0) {
                sd[NPROD * 8 + k] = use ? accv : INFINITY;
                si[NPROD * 8 + k] = use ? rr   : 0x7fffffff;
            }
        }
    }
    __syncthreads();

    // merge pool (137) -> block top-8 -> global candidates
    if (tid < 32) {
        int l = tid;
        for (int s = 0; s < 8; s++) {
            float bd = INFINITY; int bi = 0x7fffffff; int bs = -1;
            for (int k = l; k < NPOOL; k += 32)
                if (lt_pair(sd[k], si[k], bd, bi)) { bd = sd[k]; bi = si[k]; bs = k; }
            #pragma unroll
            for (int off = 16; off; off >>= 1) {
                float od = __shfl_xor_sync(0xffffffffu, bd, off);
                int   oi = __shfl_xor_sync(0xffffffffu, bi, off);
                int   os = __shfl_xor_sync(0xffffffffu, bs, off);
                if (lt_pair(od, oi, bd, bi)) { bd = od; bi = oi; bs = os; }
            }
            if (l == 0) {
                g_cand_d[b][blockIdx.x * 8 + s] = bd;
                g_cand_i[b][blockIdx.x * 8 + s] = bi;
                if (bs >= 0) sd[bs] = INFINITY;
            }
            __syncwarp();
        }
    }

    // ticket: last block of batch b does final merge + gather
    __threadfence();
    if (tid == 0) slast = (atomicAdd(&g_tick_sc[b], 1) == NBLK - 1);
    __syncthreads();
    if (!slast) return;
    if (tid == 0) g_tick_sc[b] = 0;

    if (tid < NCAND) {
        sd[tid] = __ldcg(&g_cand_d[b][tid]);
        si[tid] = __ldcg(&g_cand_i[b][tid]);
    }
    __syncthreads();

    if (tid < 32) {
        int l = tid;
        for (int s = 0; s < 8; s++) {
            float bd = INFINITY; int bi = 0x7fffffff; int bs = -1;
            for (int k = l; k < NCAND; k += 32)
                if (lt_pair(sd[k], si[k], bd, bi)) { bd = sd[k]; bi = si[k]; bs = k; }
            #pragma unroll
            for (int off = 16; off; off >>= 1) {
                float od = __shfl_xor_sync(0xffffffffu, bd, off);
                int   oi = __shfl_xor_sync(0xffffffffu, bi, off);
                int   os = __shfl_xor_sync(0xffffffffu, bs, off);
                if (lt_pair(od, oi, bd, bi)) { bd = od; bi = oi; bs = os; }
            }
            if (l == 0) { sel[s] = bi; if (bs >= 0) sd[bs] = INFINITY; }
            __syncwarp();
        }
    }
    __syncthreads();

    for (int t = tid; t < 8 * WC; t += blockDim.x) {
        int k = t >> 6, w = t & 63;
        int idx = sel[k];
        int src = -1;
        #pragma unroll
        for (int j = RR - 1; j >= 0; --j)
            if (src < 0 && srp[j] == idx) src = j;
        float v = (src >= 0) ? g_rows[b][src][w]
                             : __ldcg(&mem[((size_t)b * MROWS + idx) * WC + w]);
        out[(b * 8 + k) * WC + w] = v;
    }
}

// ================= launcher =================
extern "C" void kernel_launch(void* const* d_in, const int* in_sizes, int n_in,
                              void* d_out, int out_size) {
    const float* xi     = (const float*)d_in[0];
    const float* Wm     = (const float*)d_in[1];
    const float* b_lin  = (const float*)d_in[2];
    const float* mem    = (const float*)d_in[3];
    const float* usage  = (const float*)d_in[4];
    const float* read_w = (const float*)d_in[5];
    const float* rvec   = (const float*)d_in[7];
    const int*   rpos   = (const int*)d_in[9];
    float* out = (float*)d_out;

    static int smem_set = 0;
    if (!smem_set) {
        cudaFuncSetAttribute(k_scan, cudaFuncAttributeMaxDynamicSharedMemorySize, SMEM_DYN);
        smem_set = 1;
    }

    k_iface<<<dim3(NPART, NB), 552>>>(xi, Wm, b_lin, usage, read_w, rvec, rpos);
    k_scan<<<dim3(NBLK, NB), 256, SMEM_DYN>>>(mem, rpos, out);
}